// round 9
// baseline (speedup 1.0000x reference)
#include <cuda_runtime.h>
#include <cuda_bf16.h>
#include <cstdint>

#define NCLS 10
#define DIM  128
#define BATCH 8                       // rows per warp per iteration (MLP=8)
#define BLOCK_THREADS 256             // 8 warps
#define GRID_BLOCKS   296             // 2 blocks/SM * 148 SMs
#define TOTAL_WARPS   (GRID_BLOCKS * 8)   // 2368
#define NFINAL (NCLS * DIM + NCLS)    // 1280 sums + 10 class-S2 = 1290

// Allocation-free scratch, zeroed each launch for deterministic graph replay.
__device__ float        g_final[NFINAL];
__device__ unsigned int g_cnt[NCLS];

__global__ void CLIR_zero_kernel() {
    int i = blockIdx.x * blockDim.x + threadIdx.x;
    if (i < NFINAL) g_final[i] = 0.0f;
    if (i < NCLS)   g_cnt[i] = 0u;
}

// ---- per-class register accumulators (class is warp-uniform) --------------
// Lane l owns feature columns 4l..4l+3 of the per-class sum; q is the lane's
// partial of sum-of-squares (summed over the lane's 4 features).
#define DECL_ACC(n) float4 s##n = {0,0,0,0}; float q##n = 0.0f;

#define UPD(n, v) do {                                                   \
    s##n.x += (v).x; s##n.y += (v).y; s##n.z += (v).z; s##n.w += (v).w;  \
    float _d = fmaf((v).y,(v).y,(v).x*(v).x)                             \
             + fmaf((v).w,(v).w,(v).z*(v).z);                            \
    q##n += _d;                                                          \
} while (0)

// counts packed 2-per-register (u16 halves); per-warp per-class count << 65536
#define PROC(v, c) do { switch (c) {                                     \
    case 0: UPD(0,(v)); cnt01 += 1u;       break;                        \
    case 1: UPD(1,(v)); cnt01 += 0x10000u; break;                        \
    case 2: UPD(2,(v)); cnt23 += 1u;       break;                        \
    case 3: UPD(3,(v)); cnt23 += 0x10000u; break;                        \
    case 4: UPD(4,(v)); cnt45 += 1u;       break;                        \
    case 5: UPD(5,(v)); cnt45 += 0x10000u; break;                        \
    case 6: UPD(6,(v)); cnt67 += 1u;       break;                        \
    case 7: UPD(7,(v)); cnt67 += 0x10000u; break;                        \
    case 8: UPD(8,(v)); cnt89 += 1u;       break;                        \
    case 9: UPD(9,(v)); cnt89 += 0x10000u; break;                        \
    default: break; } } while (0)

#define FOLDC(n) do {                                                    \
    atomicAdd(&fold[(n)*DIM + 4*lane + 0], s##n.x);                      \
    atomicAdd(&fold[(n)*DIM + 4*lane + 1], s##n.y);                      \
    atomicAdd(&fold[(n)*DIM + 4*lane + 2], s##n.z);                      \
    atomicAdd(&fold[(n)*DIM + 4*lane + 3], s##n.w);                      \
    atomicAdd(&fold[NCLS*DIM + (n)], q##n);                              \
} while (0)

__global__ __launch_bounds__(BLOCK_THREADS, 2)
void CLIR_accum_kernel(const float* __restrict__ x,
                       const int*   __restrict__ t,
                       int N) {
    const int tid  = threadIdx.x;
    const int lane = tid & 31;
    const int gw   = blockIdx.x * 8 + (tid >> 5);   // global warp id

    DECL_ACC(0) DECL_ACC(1) DECL_ACC(2) DECL_ACC(3) DECL_ACC(4)
    DECL_ACC(5) DECL_ACC(6) DECL_ACC(7) DECL_ACC(8) DECL_ACC(9)
    unsigned cnt01 = 0, cnt23 = 0, cnt45 = 0, cnt67 = 0, cnt89 = 0;

    const float4* __restrict__ x4 = (const float4*)x;

    // 8 consecutive rows per warp per iteration: 8 independent LDG.128/lane
    // (4 KB in flight per warp), labels as two aligned int4 loads. No smem
    // in the hot loop; accumulation stays in registers.
    for (int base = gw * BATCH; base < N; base += TOTAL_WARPS * BATCH) {
        if (base + BATCH <= N) {
            const int4 la = __ldg((const int4*)(t + base));
            const int4 lb = __ldg((const int4*)(t + base + 4));
            const size_t r = (size_t)base * (DIM / 4) + lane;
            const float4 v0 = x4[r + 0 * 32];
            const float4 v1 = x4[r + 1 * 32];
            const float4 v2 = x4[r + 2 * 32];
            const float4 v3 = x4[r + 3 * 32];
            const float4 v4 = x4[r + 4 * 32];
            const float4 v5 = x4[r + 5 * 32];
            const float4 v6 = x4[r + 6 * 32];
            const float4 v7 = x4[r + 7 * 32];
            PROC(v0, la.x); PROC(v1, la.y); PROC(v2, la.z); PROC(v3, la.w);
            PROC(v4, lb.x); PROC(v5, lb.y); PROC(v6, lb.z); PROC(v7, lb.w);
        } else {
            for (int j = 0; base + j < N; j++) {
                const int c = __ldg(t + base + j);
                const float4 v = x4[(size_t)(base + j) * (DIM / 4) + lane];
                PROC(v, c);
            }
        }
    }

    // ---- Block fold via smem atomics (epilogue only) ----
    __shared__ float        fold[NFINAL];
    __shared__ unsigned int foldc[NCLS];
    for (int i = tid; i < NFINAL; i += BLOCK_THREADS) fold[i] = 0.0f;
    if (tid < NCLS) foldc[tid] = 0u;
    __syncthreads();

    FOLDC(0); FOLDC(1); FOLDC(2); FOLDC(3); FOLDC(4);
    FOLDC(5); FOLDC(6); FOLDC(7); FOLDC(8); FOLDC(9);
    if (lane == 0) {
        atomicAdd(&foldc[0], cnt01 & 0xFFFFu); atomicAdd(&foldc[1], cnt01 >> 16);
        atomicAdd(&foldc[2], cnt23 & 0xFFFFu); atomicAdd(&foldc[3], cnt23 >> 16);
        atomicAdd(&foldc[4], cnt45 & 0xFFFFu); atomicAdd(&foldc[5], cnt45 >> 16);
        atomicAdd(&foldc[6], cnt67 & 0xFFFFu); atomicAdd(&foldc[7], cnt67 >> 16);
        atomicAdd(&foldc[8], cnt89 & 0xFFFFu); atomicAdd(&foldc[9], cnt89 >> 16);
    }
    __syncthreads();

    // ---- Global spread atomics (REDG): 1290 + 10 per block ----
    for (int i = tid; i < NFINAL; i += BLOCK_THREADS)
        atomicAdd(&g_final[i], fold[i]);
    if (tid < NCLS)
        atomicAdd(&g_cnt[tid], foldc[tid]);
}

// penalty = (1/C) * Σ_c [ S2_c/(n_c-1) - Σ_d sum[c][d]^2 / (n_c (n_c-1)) ]
__global__ void CLIR_finalize_kernel(float* __restrict__ out) {
    __shared__ float scnt[NCLS];
    const int d = threadIdx.x;   // 128 threads
    if (d < NCLS) scnt[d] = (float)g_cnt[d];
    __syncthreads();

    float p = 0.0f;
    #pragma unroll
    for (int c = 0; c < NCLS; c++) {
        const float n = scnt[c];
        const float s = g_final[c * DIM + d];
        p += (s * s) / (n * (n - 1.0f));
    }
    #pragma unroll
    for (int o = 16; o > 0; o >>= 1)
        p += __shfl_xor_sync(0xFFFFFFFFu, p, o);
    __shared__ float wr[4];
    if ((d & 31) == 0) wr[d >> 5] = p;
    __syncthreads();
    if (d == 0) {
        float tr = 0.0f;
        #pragma unroll
        for (int c = 0; c < NCLS; c++)
            tr += g_final[NCLS * DIM + c] / (scnt[c] - 1.0f);
        out[0] = (tr - (wr[0] + wr[1] + wr[2] + wr[3])) * (1.0f / (float)NCLS);
    }
}

extern "C" void kernel_launch(void* const* d_in, const int* in_sizes, int n_in,
                              void* d_out, int out_size) {
    const float* x = (const float*)d_in[0];
    const int*   t = (const int*)d_in[1];
    const int N = in_sizes[1];

    CLIR_zero_kernel<<<(NFINAL + 255) / 256, 256>>>();
    CLIR_accum_kernel<<<GRID_BLOCKS, BLOCK_THREADS>>>(x, t, N);
    CLIR_finalize_kernel<<<1, DIM>>>((float*)d_out);
}